// round 15
// baseline (speedup 1.0000x reference)
#include <cuda_runtime.h>
#include <cuda_fp16.h>
#include <math.h>
#include <stdint.h>

#define E_   1024
#define NH   16
#define HD   64
#define WIN  256
#define BB   8
#define SS   1024
#define BS   (BB*SS)
#define FF   4096

// ---------------- scratch ------------------------------------------------------
__device__ float g_tmp[BS*E_];
__device__ float g_x1[BS*E_];

__device__ __half g_a1h[BS*E_];
__device__ __half g_a2h[BS*E_];
__device__ __half g_x1h[BS*E_];
__device__ __half g_hh[(size_t)BS*FF];
__device__ __half g_qkh[(size_t)BS*2*E_];
__device__ __half g_vh[BS*E_];
__device__ __half g_wih[3*E_*E_];
__device__ __half g_woh[E_*E_];
__device__ __half g_w1h[FF*E_];
__device__ __half g_w2h[FF*E_];

// ---------------- streams/events -------------------------------------------------
struct StreamPack {
    cudaStream_t s2;
    cudaEvent_t eStart, eR, eWih, eV, eW2;
    StreamPack() {
        cudaStreamCreateWithFlags(&s2, cudaStreamNonBlocking);
        cudaEventCreateWithFlags(&eStart, cudaEventDisableTiming);
        cudaEventCreateWithFlags(&eR,     cudaEventDisableTiming);
        cudaEventCreateWithFlags(&eWih,   cudaEventDisableTiming);
        cudaEventCreateWithFlags(&eV,     cudaEventDisableTiming);
        cudaEventCreateWithFlags(&eW2,    cudaEventDisableTiming);
    }
};
static StreamPack g_sp;

// ---------------- helpers -------------------------------------------------------
__device__ __forceinline__ uint32_t smem_u32(const void* p) {
    uint32_t a;
    asm("{ .reg .u64 t; cvta.to.shared.u64 t, %1; cvt.u32.u64 %0, t; }" : "=r"(a) : "l"(p));
    return a;
}
__device__ __forceinline__ void cp16(uint32_t dst, const void* src) {
    asm volatile("cp.async.cg.shared.global [%0], [%1], 16;" :: "r"(dst), "l"(src));
}
__device__ __forceinline__ void cp_commit() { asm volatile("cp.async.commit_group;"); }
__device__ __forceinline__ void cp_wait1()  { asm volatile("cp.async.wait_group 1;" ::: "memory"); }
__device__ __forceinline__ void ldm_x4(uint32_t addr, uint32_t& r0, uint32_t& r1,
                                       uint32_t& r2, uint32_t& r3) {
    asm volatile("ldmatrix.sync.aligned.m8n8.x4.shared.b16 {%0,%1,%2,%3}, [%4];"
                 : "=r"(r0), "=r"(r1), "=r"(r2), "=r"(r3) : "r"(addr));
}
__device__ __forceinline__ void ldm_x4t(uint32_t addr, uint32_t& r0, uint32_t& r1,
                                        uint32_t& r2, uint32_t& r3) {
    asm volatile("ldmatrix.sync.aligned.m8n8.x4.trans.shared.b16 {%0,%1,%2,%3}, [%4];"
                 : "=r"(r0), "=r"(r1), "=r"(r2), "=r"(r3) : "r"(addr));
}
__device__ __forceinline__ void mma16816(float* c, const uint32_t* a, const uint32_t* b) {
    asm volatile(
        "mma.sync.aligned.m16n8k16.row.col.f32.f16.f16.f32 "
        "{%0,%1,%2,%3}, {%4,%5,%6,%7}, {%8,%9}, {%0,%1,%2,%3};"
        : "+f"(c[0]), "+f"(c[1]), "+f"(c[2]), "+f"(c[3])
        : "r"(a[0]), "r"(a[1]), "r"(a[2]), "r"(a[3]), "r"(b[0]), "r"(b[1]));
}
__device__ __forceinline__ uint32_t pack_h2(float a, float b) {
    __half2 h = __floats2half2_rn(a, b);
    return *(uint32_t*)&h;
}

// ---------------- convert fp32 -> fp16 -------------------------------------------
__global__ __launch_bounds__(256) void conv_kernel(const float* __restrict__ src,
                                                   __half* __restrict__ hi)
{
    size_t i = ((size_t)blockIdx.x * 256 + threadIdx.x) * 4;
    float4 v = *(const float4*)&src[i];
    uint2 ho;
    ho.x = pack_h2(v.x, v.y);
    ho.y = pack_h2(v.z, v.w);
    *(uint2*)&hi[i] = ho;
}

// ---------------- RoPE on raw x -> fp16 roped + fp16 plain -----------------------
__global__ __launch_bounds__(256) void rope_conv_kernel(const float* __restrict__ x,
                                                        __half* __restrict__ hi,
                                                        __half* __restrict__ xh)
{
    int tok = blockIdx.x;
    float pos = (float)(tok & (SS - 1));
    int base = tok * E_ + threadIdx.x * 4;
    int d = (threadIdx.x * 4) & (HD - 1);
    const float* xp = &x[base];
    float4 xv = *(const float4*)xp;
    float res[4];
    const float LOG2_10000 = 13.287712379549449f;
#pragma unroll
    for (int i = 0; i < 4; i++) {
        int dd = d + i;
        int j = (dd < 32) ? dd : dd - 32;
        float fr = exp2f(-(float)j * (2.0f / 64.0f) * LOG2_10000);
        float ang = pos * fr;
        float s, c;
        sincosf(ang, &s, &c);
        float v = ((const float*)&xv)[i];
        float other = (dd < 32) ? -xp[i + 32] : xp[i - 32];
        res[i] = v * c + other * s;
    }
    uint2 ho, xo;
    ho.x = pack_h2(res[0], res[1]);
    ho.y = pack_h2(res[2], res[3]);
    xo.x = pack_h2(xv.x, xv.y);
    xo.y = pack_h2(xv.z, xv.w);
    *(uint2*)&hi[base] = ho;
    *(uint2*)&xh[base] = xo;
}

// ---------------- HMMA fp16 GEMM: 128x128 CTA, BK=32, 6 stages, paired chunks ----
// R11 chunk body, but ONE wait_group+barrier per TWO chunks (6-stage ring).
// Safety: issues for chunks c+4,c+5 hit stages (c-2)%6,(c-1)%6 whose reads ended
// before the previous pair's end barrier; wait_group 1 at pair end leaves only
// the newest group pending, so chunks <= c+4 are resident for the next pair's
// fragment prefetches (c+1 is always resident, c+2 resident from previous wait).
#define STG6 6
#define BOFF6 (STG6 * 8192)
#define GEMM_SMEM (2 * STG6 * 8192)

template<int ACT, int MODE>
__global__ __launch_bounds__(256, 2) void gemm_mma_kernel(
    const __half* __restrict__ Ah, const __half* __restrict__ Bh,
    const float* __restrict__ bias, float* __restrict__ C,
    __half* __restrict__ Ch,
    int M, int N, int K)
{
    extern __shared__ __align__(16) char smc[];
    uint32_t sbase = smem_u32(smc);

    int t = threadIdx.x;
    int lane = t & 31, wid = t >> 5;
    int warp_m = wid & 3, warp_n = wid >> 2;
    int m0 = blockIdx.y * 128;
    int n0 = blockIdx.x * 128;

    uint32_t aOff[2];
    size_t   aG[2], bG[2];
#pragma unroll
    for (int i = 0; i < 2; i++) {
        int idx = t + i * 256;
        int row = idx >> 2, ch = idx & 3;
        uint32_t swz = (uint32_t)(ch ^ ((row >> 1) & 3));
        aOff[i] = (uint32_t)(row * 64) + swz * 16;
        aG[i] = (size_t)(m0 + row) * K + ch * 8;
        bG[i] = (size_t)(n0 + row) * K + ch * 8;
    }

    uint32_t aRow64[2]; int aRswz[2];
#pragma unroll
    for (int ti = 0; ti < 2; ti++) {
        int row = warp_m * 32 + ti * 16 + (lane & 15);
        aRow64[ti] = (uint32_t)(row * 64);
        aRswz[ti] = (row >> 1) & 3;
    }
    int aChunkBase = lane >> 4;
    uint32_t bRow64[4]; int bRswz[4];
#pragma unroll
    for (int j2 = 0; j2 < 4; j2++) {
        int row = warp_n * 64 + j2 * 16 + ((lane >> 4) << 3) + (lane & 7);
        bRow64[j2] = (uint32_t)(row * 64);
        bRswz[j2] = (row >> 1) & 3;
    }
    int bChunkBase = (lane >> 3) & 1;

    float acc[2][8][4];
#pragma unroll
    for (int mi = 0; mi < 2; mi++)
#pragma unroll
        for (int nj = 0; nj < 8; nj++)
#pragma unroll
            for (int r = 0; r < 4; r++) acc[mi][nj][r] = 0.f;

    int NC = K >> 5;   // always even (K = 1024 or 4096)

    // prologue: issue chunks 0..3 -> stages 0..3 (one group each)
#pragma unroll
    for (int p = 0; p < 4; p++) {
        size_t ko = (size_t)p * 32;
        uint32_t sa = sbase + (uint32_t)p * 8192;
        uint32_t sb = sbase + BOFF6 + (uint32_t)p * 8192;
#pragma unroll
        for (int i = 0; i < 2; i++) cp16(sa + aOff[i], Ah + aG[i] + ko);
#pragma unroll
        for (int i = 0; i < 2; i++) cp16(sb + aOff[i], Bh + bG[i] + ko);
        cp_commit();
    }
    cp_wait1();          // chunks 0..2 complete (this thread)
    __syncthreads();     // ... and visible

    uint32_t a0[2][4], b0[4][4];
    uint32_t a1[2][4], b1[4][4];

    // preload frag(chunk 0, kstep 0)
    {
        uint32_t sa = sbase, sb = sbase + BOFF6;
#pragma unroll
        for (int ti = 0; ti < 2; ti++) {
            int ch = aChunkBase;
            ldm_x4(sa + aRow64[ti] + (uint32_t)((ch ^ aRswz[ti]) * 16),
                   a0[ti][0], a0[ti][1], a0[ti][2], a0[ti][3]);
        }
#pragma unroll
        for (int j2 = 0; j2 < 4; j2++) {
            int ch = bChunkBase;
            ldm_x4(sb + bRow64[j2] + (uint32_t)((ch ^ bRswz[j2]) * 16),
                   b0[j2][0], b0[j2][1], b0[j2][2], b0[j2][3]);
        }
    }

    // super-iterations over chunk pairs (c, c+1)
    for (int c = 0; c < NC; c += 2) {
        // issue chunks c+4, c+5 (one group each; empty-commit at tail is fine)
#pragma unroll
        for (int q = 4; q <= 5; q++) {
            if (c + q < NC) {
                size_t ko = (size_t)(c + q) * 32;
                uint32_t st = (uint32_t)((c + q) % STG6);
                uint32_t sa3 = sbase + st * 8192;
                uint32_t sb3 = sbase + BOFF6 + st * 8192;
#pragma unroll
                for (int i = 0; i < 2; i++) cp16(sa3 + aOff[i], Ah + aG[i] + ko);
#pragma unroll
                for (int i = 0; i < 2; i++) cp16(sb3 + aOff[i], Bh + bG[i] + ko);
            }
            cp_commit();
        }

        // two chunks, R11-style fragment pipelining
#pragma unroll
        for (int sub = 0; sub < 2; sub++) {
            int cc = c + sub;
            uint32_t sa = sbase + (uint32_t)(cc % STG6) * 8192;
            uint32_t sb = sbase + BOFF6 + (uint32_t)(cc % STG6) * 8192;

            // LDSM frag(cc, k1)
#pragma unroll
            for (int ti = 0; ti < 2; ti++) {
                int ch = 2 + aChunkBase;
                ldm_x4(sa + aRow64[ti] + (uint32_t)((ch ^ aRswz[ti]) * 16),
                       a1[ti][0], a1[ti][1], a1[ti][2], a1[ti][3]);
            }
#pragma unroll
            for (int j2 = 0; j2 < 4; j2++) {
                int ch = 2 + bChunkBase;
                ldm_x4(sb + bRow64[j2] + (uint32_t)((ch ^ bRswz[j2]) * 16),
                       b1[j2][0], b1[j2][1], b1[j2][2], b1[j2][3]);
            }

            // MMA kstep 0
#pragma unroll
            for (int mi = 0; mi < 2; mi++)
#pragma unroll
                for (int nj = 0; nj < 8; nj++)
                    mma16816(acc[mi][nj], a0[mi], &b0[nj >> 1][(nj & 1) * 2]);

            // preload frag(cc+1, k0) — stage cc+1 resident & visible
            if (cc + 1 < NC) {
                uint32_t sa2 = sbase + (uint32_t)((cc + 1) % STG6) * 8192;
                uint32_t sb2 = sbase + BOFF6 + (uint32_t)((cc + 1) % STG6) * 8192;
#pragma unroll
                for (int ti = 0; ti < 2; ti++) {
                    int ch = aChunkBase;
                    ldm_x4(sa2 + aRow64[ti] + (uint32_t)((ch ^ aRswz[ti]) * 16),
                           a0[ti][0], a0[ti][1], a0[ti][2], a0[ti][3]);
                }
#pragma unroll
                for (int j2 = 0; j2 < 4; j2++) {
                    int ch = bChunkBase;
                    ldm_x4(sb2 + bRow64[j2] + (uint32_t)((ch ^ bRswz[j2]) * 16),
                           b0[j2][0], b0[j2][1], b0[j2][2], b0[j2][3]);
                }
            }

            // MMA kstep 1
#pragma unroll
            for (int mi = 0; mi < 2; mi++)
#pragma unroll
                for (int nj = 0; nj < 8; nj++)
                    mma16816(acc[mi][nj], a1[mi], &b1[nj >> 1][(nj & 1) * 2]);
        }

        // ONE wait + barrier per pair
        cp_wait1();
        __syncthreads();
    }

    int tq = lane >> 2, tr = lane & 3;
#pragma unroll
    for (int mi = 0; mi < 2; mi++) {
#pragma unroll
        for (int nj = 0; nj < 8; nj++) {
            int row0 = m0 + warp_m * 32 + mi * 16 + tq;
            int col = n0 + warp_n * 64 + nj * 8 + tr * 2;
            float c0 = __ldg(&bias[col]), c1 = __ldg(&bias[col + 1]);
            float v0 = acc[mi][nj][0] + c0, v1 = acc[mi][nj][1] + c1;
            float v2 = acc[mi][nj][2] + c0, v3 = acc[mi][nj][3] + c1;
            if (ACT) {
                v0 = 0.5f * v0 * (1.0f + erff(v0 * 0.70710678118654752f));
                v1 = 0.5f * v1 * (1.0f + erff(v1 * 0.70710678118654752f));
                v2 = 0.5f * v2 * (1.0f + erff(v2 * 0.70710678118654752f));
                v3 = 0.5f * v3 * (1.0f + erff(v3 * 0.70710678118654752f));
            }
            if (MODE == 0) {
                *(float2*)&C[(size_t)row0 * N + col] = make_float2(v0, v1);
                *(float2*)&C[(size_t)(row0 + 8) * N + col] = make_float2(v2, v3);
            } else {
                *(uint32_t*)&Ch[(size_t)row0 * N + col] = pack_h2(v0, v1);
                *(uint32_t*)&Ch[(size_t)(row0 + 8) * N + col] = pack_h2(v2, v3);
            }
        }
    }
}

// ---------------- tensor-core flash attention: 128-q tile, 256 thr, 8 warps ------
__global__ __launch_bounds__(256) void attn_mma_kernel(
    const __half* __restrict__ qk,   // [BS][2E] : Q | K
    const __half* __restrict__ v,    // [BS][E]
    __half* __restrict__ ch)         // ctx [BS][E]
{
    __shared__ __align__(16) __half q_s[128 * 64];
    __shared__ __align__(16) __half k_s[64 * 64];
    __shared__ __align__(16) __half v_s[64 * 64];

    int b = blockIdx.z, h = blockIdx.y;
    int q0 = blockIdx.x * 128;
    int t = threadIdx.x;
    int lane = t & 31, w = t >> 5;
    uint32_t sq = smem_u32(q_s), sk = smem_u32(k_s), sv = smem_u32(v_s);

#pragma unroll
    for (int i = 0; i < 4; i++) {
        int idx = t + i * 256;
        int r = idx >> 3, c = idx & 7;
        *(uint4*)((char*)q_s + r * 128 + ((c ^ (r & 7)) * 16)) =
            *(const uint4*)&qk[(size_t)(b * SS + q0 + r) * (2 * E_) + h * HD + c * 8];
    }
    __syncthreads();

    uint32_t qa[4][4];
#pragma unroll
    for (int kc = 0; kc < 4; kc++) {
        int m = lane >> 3;
        int rr = w * 16 + (lane & 7) + ((m & 1) ? 8 : 0);
        int cc = kc * 2 + (m >> 1);
        uint32_t addr = sq + (uint32_t)(rr * 128 + ((cc ^ (rr & 7)) * 16));
        ldm_x4(addr, qa[kc][0], qa[kc][1], qa[kc][2], qa[kc][3]);
    }

    float o[8][4];
#pragma unroll
    for (int d = 0; d < 8; d++)
#pragma unroll
        for (int r = 0; r < 4; r++) o[d][r] = 0.f;
    float mrow[2] = {-1e30f, -1e30f};
    float lsum[2] = {0.f, 0.f};

    int kstart = q0 - WIN; if (kstart < 0) kstart = 0;
    int kend = q0 + 128 + WIN; if (kend > SS) kend = SS;
    const float scale = 0.125f;
    int tq = lane >> 2, tr = lane & 3;

    for (int kb = kstart; kb < kend; kb += 64) {
        __syncthreads();
#pragma unroll
        for (int i = 0; i < 2; i++) {
            int idx = t + i * 256;
            int r = idx >> 3, c = idx & 7;
            uint32_t so = (uint32_t)(r * 128 + ((c ^ (r & 7)) * 16));
            *(uint4*)((char*)k_s + so) =
                *(const uint4*)&qk[(size_t)(b * SS + kb + r) * (2 * E_) + E_ + h * HD + c * 8];
            *(uint4*)((char*)v_s + so) =
                *(const uint4*)&v[(size_t)(b * SS + kb + r) * E_ + h * HD + c * 8];
        }
        __syncthreads();

        float s[8][4];
#pragma unroll
        for (int j = 0; j < 8; j++)
#pragma unroll
            for (int r = 0; r < 4; r++) s[j][r] = 0.f;
#pragma unroll
        for (int kc = 0; kc < 4; kc++) {
#pragma unroll
            for (int j2 = 0; j2 < 4; j2++) {
                int m = lane >> 3;
                int rr = j2 * 16 + (lane & 7) + ((m >= 2) ? 8 : 0);
                int cc = kc * 2 + (m & 1);
                uint32_t addr = sk + (uint32_t)(rr * 128 + ((cc ^ (rr & 7)) * 16));
                uint32_t b0, b1, b2, b3;
                ldm_x4(addr, b0, b1, b2, b3);
                uint32_t bj[2] = {b0, b1}, bj1[2] = {b2, b3};
                mma16816(s[2 * j2],     qa[kc], bj);
                mma16816(s[2 * j2 + 1], qa[kc], bj1);
            }
        }

#pragma unroll
        for (int e = 0; e < 2; e++) {
            int qi = q0 + w * 16 + tq + e * 8;
            float rmax = -1e30f;
#pragma unroll
            for (int j = 0; j < 8; j++) {
#pragma unroll
                for (int u = 0; u < 2; u++) {
                    int col = kb + j * 8 + tr * 2 + u;
                    int diff = qi - col;
                    bool ok = (diff <= WIN) && (diff >= -WIN);
                    float val = ok ? s[j][e * 2 + u] * scale : -1e30f;
                    s[j][e * 2 + u] = val;
                    rmax = fmaxf(rmax, val);
                }
            }
            rmax = fmaxf(rmax, __shfl_xor_sync(0xffffffffu, rmax, 1));
            rmax = fmaxf(rmax, __shfl_xor_sync(0xffffffffu, rmax, 2));
            float mnew = fmaxf(mrow[e], rmax);
            float corr = __expf(mrow[e] - mnew);
            float rsum = 0.f;
#pragma unroll
            for (int j = 0; j < 8; j++) {
#pragma unroll
                for (int u = 0; u < 2; u++) {
                    float p = __expf(s[j][e * 2 + u] - mnew);
                    s[j][e * 2 + u] = p;
                    rsum += p;
                }
            }
            rsum += __shfl_xor_sync(0xffffffffu, rsum, 1);
            rsum += __shfl_xor_sync(0xffffffffu, rsum, 2);
            mrow[e] = mnew;
            lsum[e] = lsum[e] * corr + rsum;
#pragma unroll
            for (int d = 0; d < 8; d++) {
                o[d][e * 2] *= corr;
                o[d][e * 2 + 1] *= corr;
            }
        }

#pragma unroll
        for (int kc = 0; kc < 4; kc++) {
            uint32_t pa[4];
            pa[0] = pack_h2(s[2 * kc][0],     s[2 * kc][1]);
            pa[1] = pack_h2(s[2 * kc][2],     s[2 * kc][3]);
            pa[2] = pack_h2(s[2 * kc + 1][0], s[2 * kc + 1][1]);
            pa[3] = pack_h2(s[2 * kc + 1][2], s[2 * kc + 1][3]);
#pragma unroll
            for (int d2 = 0; d2 < 4; d2++) {
                int m = lane >> 3;
                int rr = kc * 16 + (lane & 7) + ((m & 1) ? 8 : 0);
                int cc = 2 * d2 + (m >> 1);
                uint32_t addr = sv + (uint32_t)(rr * 128 + ((cc ^ (rr & 7)) * 16));
                uint32_t b0, b1, b2, b3;
                ldm_x4t(addr, b0, b1, b2, b3);
                uint32_t bd[2] = {b0, b1}, bd1[2] = {b2, b3};
                mma16816(o[2 * d2],     pa, bd);
                mma16816(o[2 * d2 + 1], pa, bd1);
            }
        }
    }

    float inv0 = 1.f / lsum[0], inv1 = 1.f / lsum[1];
#pragma unroll
    for (int d = 0; d < 8; d++) {
        int row0 = q0 + w * 16 + tq;
        int col = h * HD + d * 8 + tr * 2;
        *(uint32_t*)&ch[(size_t)(b * SS + row0) * E_ + col] =
            pack_h2(o[d][0] * inv0, o[d][1] * inv0);
        *(uint32_t*)&ch[(size_t)(b * SS + row0 + 8) * E_ + col] =
            pack_h2(o[d][2] * inv1, o[d][3] * inv1);
    }
}

// ---------------- residual add + LayerNorm (optional fused fp16 out) -------------
__global__ __launch_bounds__(256) void add_ln_kernel(
    const float* __restrict__ a, const float* __restrict__ r,
    const float* __restrict__ g, const float* __restrict__ be,
    float* __restrict__ out, __half* __restrict__ oh)
{
    int row = blockIdx.x;
    int t = threadIdx.x;
    size_t base = (size_t)row * E_;
    float4 av = *(const float4*)&a[base + t * 4];
    float4 rv = *(const float4*)&r[base + t * 4];
    float v0 = av.x + rv.x, v1 = av.y + rv.y, v2 = av.z + rv.z, v3 = av.w + rv.w;
    float sum = v0 + v1 + v2 + v3;
    float sq = v0 * v0 + v1 * v1 + v2 * v2 + v3 * v3;
#pragma unroll
    for (int off = 16; off; off >>= 1) {
        sum += __shfl_xor_sync(0xffffffffu, sum, off);
        sq  += __shfl_xor_sync(0xffffffffu, sq, off);
    }
    __shared__ float ss[8], sq2[8], stat[2];
    int w = t >> 5;
    if ((t & 31) == 0) { ss[w] = sum; sq2[w] = sq; }
    __syncthreads();
    if (t == 0) {
        float S1 = 0.f, S2 = 0.f;
        for (int i = 0; i < 8; i++) { S1 += ss[i]; S2 += sq2[i]; }
        float mean = S1 * (1.0f / E_);
        float var = S2 * (1.0f / E_) - mean * mean;
        stat[0] = mean;
        stat[1] = rsqrtf(var + 1e-5f);
    }
    __syncthreads();
    float mean = stat[0], rstd = stat[1];
    float4 gv = *(const float4*)&g[t * 4];
    float4 bv = *(const float4*)&be[t * 4];
    float o[4];
    o[0] = (v0 - mean) * rstd * gv.x + bv.x;
    o[1] = (v1 - mean) * rstd * gv.y + bv.y;
    o[2] = (v2 - mean) * rstd * gv.z + bv.z;
    o[3] = (v3 - mean) * rstd * gv.w + bv.w;
    *(float4*)&out[base + t * 4] = make_float4(o[0], o[1], o[2], o[3]);
    if (oh) {
        uint2 ho;
        ho.x = pack_h2(o[0], o[1]);
        ho.y = pack_h2(o[2], o[3]);
        *(uint2*)&oh[base + t * 4] = ho;
    }
}

// ---------------- launch ---------------------------------------------------------
extern "C" void kernel_launch(void* const* d_in, const int* in_sizes, int n_in,
                              void* d_out, int out_size)
{
    (void)in_sizes; (void)n_in; (void)out_size;
    const float* x    = (const float*)d_in[0];
    const float* ipw  = (const float*)d_in[1];
    const float* ipb  = (const float*)d_in[2];
    const float* opw  = (const float*)d_in[3];
    const float* opb  = (const float*)d_in[4];
    const float* ln1g = (const float*)d_in[5];
    const float* ln1b = (const float*)d_in[6];
    const float* w1   = (const float*)d_in[7];
    const float* b1   = (const float*)d_in[8];
    const float* w2   = (const float*)d_in[9];
    const float* b2   = (const float*)d_in[10];
    const float* ln2g = (const float*)d_in[11];
    const float* ln2b = (const float*)d_in[12];
    float* out = (float*)d_out;

    float *tmp, *x1;
    cudaGetSymbolAddress((void**)&tmp, g_tmp);
    cudaGetSymbolAddress((void**)&x1,  g_x1);

    __half *a1h, *a2h, *x1h, *hh, *qkh, *vh, *wih, *woh, *w1h, *w2h;
    cudaGetSymbolAddress((void**)&a1h, g_a1h);
    cudaGetSymbolAddress((void**)&a2h, g_a2h);
    cudaGetSymbolAddress((void**)&x1h, g_x1h);
    cudaGetSymbolAddress((void**)&hh,  g_hh);
    cudaGetSymbolAddress((void**)&qkh, g_qkh);
    cudaGetSymbolAddress((void**)&vh,  g_vh);
    cudaGetSymbolAddress((void**)&wih, g_wih); cudaGetSymbolAddress((void**)&woh, g_woh);
    cudaGetSymbolAddress((void**)&w1h, g_w1h); cudaGetSymbolAddress((void**)&w2h, g_w2h);

    cudaFuncSetAttribute(gemm_mma_kernel<0,0>,
                         cudaFuncAttributeMaxDynamicSharedMemorySize, GEMM_SMEM);
    cudaFuncSetAttribute(gemm_mma_kernel<0,1>,
                         cudaFuncAttributeMaxDynamicSharedMemorySize, GEMM_SMEM);
    cudaFuncSetAttribute(gemm_mma_kernel<1,1>,
                         cudaFuncAttributeMaxDynamicSharedMemorySize, GEMM_SMEM);

    cudaStream_t s0 = 0, s2 = g_sp.s2;

    cudaEventRecord(g_sp.eStart, s0);
    cudaStreamWaitEvent(s2, g_sp.eStart, 0);

    // 0: RoPE(x) -> a1h, fp16 x -> a2h   (s0)
    rope_conv_kernel<<<BS, 256, 0, s0>>>(x, a1h, a2h);
    cudaEventRecord(g_sp.eR, s0);

    // 1: in_proj weight conv (s2)
    conv_kernel<<<(3 * E_ * E_) / 1024, 256, 0, s2>>>(ipw, wih);
    cudaEventRecord(g_sp.eWih, s2);

    // 2: fused Q|K GEMM (s0)
    cudaStreamWaitEvent(s0, g_sp.eWih, 0);
    gemm_mma_kernel<0,1><<<dim3(16, 64), 256, GEMM_SMEM, s0>>>(
        a1h, wih, ipb, nullptr, qkh, BS, 2 * E_, E_);

    // 3: V GEMM (s2)
    cudaStreamWaitEvent(s2, g_sp.eR, 0);
    gemm_mma_kernel<0,1><<<dim3(8, 64), 256, GEMM_SMEM, s2>>>(
        a2h, wih + (size_t)2*E_*E_, ipb + 2 * E_, nullptr, vh, BS, E_, E_);
    cudaEventRecord(g_sp.eV, s2);

    // 4: out_proj weight conv (s2)
    conv_kernel<<<(E_ * E_) / 1024, 256, 0, s2>>>(opw, woh);

    // 5: attention (s0) -> ctx into a2h
    cudaStreamWaitEvent(s0, g_sp.eV, 0);
    attn_mma_kernel<<<dim3(SS / 128, NH, BB), 256, 0, s0>>>(qkh, vh, a2h);

    // 6,7: FFN weight convs (s2)
    conv_kernel<<<(FF * E_) / 1024, 256, 0, s2>>>(w1, w1h);
    conv_kernel<<<(FF * E_) / 1024, 256, 0, s2>>>(w2, w2h);
    cudaEventRecord(g_sp.eW2, s2);

    cudaStreamWaitEvent(s0, g_sp.eW2, 0);

    // 8: out-proj GEMM; 9: LN1
    gemm_mma_kernel<0,0><<<dim3(8, 64), 256, GEMM_SMEM, s0>>>(
        a2h, woh, opb, tmp, nullptr, BS, E_, E_);
    add_ln_kernel<<<BS, 256, 0, s0>>>(x, tmp, ln1g, ln1b, x1, x1h);

    // 10-12: FFN + LN2
    gemm_mma_kernel<1,1><<<dim3(32, 64), 256, GEMM_SMEM, s0>>>(
        x1h, w1h, b1, nullptr, hh, BS, FF, E_);
    gemm_mma_kernel<0,0><<<dim3(8, 64), 256, GEMM_SMEM, s0>>>(
        hh, w2h, b2, tmp, nullptr, BS, E_, FF);
    add_ln_kernel<<<BS, 256, 0, s0>>>(x1, tmp, ln2g, ln2b, out, nullptr);
}

// round 16
// speedup vs baseline: 1.1318x; 1.1318x over previous
#include <cuda_runtime.h>
#include <cuda_fp16.h>
#include <math.h>
#include <stdint.h>

#define E_   1024
#define NH   16
#define HD   64
#define WIN  256
#define BB   8
#define SS   1024
#define BS   (BB*SS)
#define FF   4096

// ---------------- scratch ------------------------------------------------------
__device__ float g_tmp[BS*E_];
__device__ float g_x1[BS*E_];

__device__ __half g_a1h[BS*E_];
__device__ __half g_a2h[BS*E_];
__device__ __half g_x1h[BS*E_];
__device__ __half g_hh[(size_t)BS*FF];
__device__ __half g_qkh[(size_t)BS*2*E_];
__device__ __half g_vh[BS*E_];
__device__ __half g_wih[3*E_*E_];
__device__ __half g_woh[E_*E_];
__device__ __half g_w1h[FF*E_];
__device__ __half g_w2h[FF*E_];

// ---------------- streams/events -------------------------------------------------
struct StreamPack {
    cudaStream_t s2;
    cudaEvent_t eStart, eR, eWih, eV, eW2;
    StreamPack() {
        cudaStreamCreateWithFlags(&s2, cudaStreamNonBlocking);
        cudaEventCreateWithFlags(&eStart, cudaEventDisableTiming);
        cudaEventCreateWithFlags(&eR,     cudaEventDisableTiming);
        cudaEventCreateWithFlags(&eWih,   cudaEventDisableTiming);
        cudaEventCreateWithFlags(&eV,     cudaEventDisableTiming);
        cudaEventCreateWithFlags(&eW2,    cudaEventDisableTiming);
    }
};
static StreamPack g_sp;

// ---------------- helpers -------------------------------------------------------
__device__ __forceinline__ uint32_t smem_u32(const void* p) {
    uint32_t a;
    asm("{ .reg .u64 t; cvta.to.shared.u64 t, %1; cvt.u32.u64 %0, t; }" : "=r"(a) : "l"(p));
    return a;
}
__device__ __forceinline__ void cp16(uint32_t dst, const void* src) {
    asm volatile("cp.async.cg.shared.global [%0], [%1], 16;" :: "r"(dst), "l"(src));
}
__device__ __forceinline__ void cp_commit() { asm volatile("cp.async.commit_group;"); }
__device__ __forceinline__ void cp_wait1()  { asm volatile("cp.async.wait_group 1;" ::: "memory"); }
__device__ __forceinline__ void ldm_x4(uint32_t addr, uint32_t& r0, uint32_t& r1,
                                       uint32_t& r2, uint32_t& r3) {
    asm volatile("ldmatrix.sync.aligned.m8n8.x4.shared.b16 {%0,%1,%2,%3}, [%4];"
                 : "=r"(r0), "=r"(r1), "=r"(r2), "=r"(r3) : "r"(addr));
}
__device__ __forceinline__ void ldm_x4t(uint32_t addr, uint32_t& r0, uint32_t& r1,
                                        uint32_t& r2, uint32_t& r3) {
    asm volatile("ldmatrix.sync.aligned.m8n8.x4.trans.shared.b16 {%0,%1,%2,%3}, [%4];"
                 : "=r"(r0), "=r"(r1), "=r"(r2), "=r"(r3) : "r"(addr));
}
__device__ __forceinline__ void mma16816(float* c, const uint32_t* a, const uint32_t* b) {
    asm volatile(
        "mma.sync.aligned.m16n8k16.row.col.f32.f16.f16.f32 "
        "{%0,%1,%2,%3}, {%4,%5,%6,%7}, {%8,%9}, {%0,%1,%2,%3};"
        : "+f"(c[0]), "+f"(c[1]), "+f"(c[2]), "+f"(c[3])
        : "r"(a[0]), "r"(a[1]), "r"(a[2]), "r"(a[3]), "r"(b[0]), "r"(b[1]));
}
__device__ __forceinline__ uint32_t pack_h2(float a, float b) {
    __half2 h = __floats2half2_rn(a, b);
    return *(uint32_t*)&h;
}

// ---------------- convert fp32 -> fp16 -------------------------------------------
__global__ __launch_bounds__(256) void conv_kernel(const float* __restrict__ src,
                                                   __half* __restrict__ hi)
{
    size_t i = ((size_t)blockIdx.x * 256 + threadIdx.x) * 4;
    float4 v = *(const float4*)&src[i];
    uint2 ho;
    ho.x = pack_h2(v.x, v.y);
    ho.y = pack_h2(v.z, v.w);
    *(uint2*)&hi[i] = ho;
}

// ---------------- RoPE on raw x -> fp16 roped + fp16 plain -----------------------
__global__ __launch_bounds__(256) void rope_conv_kernel(const float* __restrict__ x,
                                                        __half* __restrict__ hi,
                                                        __half* __restrict__ xh)
{
    int tok = blockIdx.x;
    float pos = (float)(tok & (SS - 1));
    int base = tok * E_ + threadIdx.x * 4;
    int d = (threadIdx.x * 4) & (HD - 1);
    const float* xp = &x[base];
    float4 xv = *(const float4*)xp;
    float res[4];
    const float LOG2_10000 = 13.287712379549449f;
#pragma unroll
    for (int i = 0; i < 4; i++) {
        int dd = d + i;
        int j = (dd < 32) ? dd : dd - 32;
        float fr = exp2f(-(float)j * (2.0f / 64.0f) * LOG2_10000);
        float ang = pos * fr;
        float s, c;
        sincosf(ang, &s, &c);
        float v = ((const float*)&xv)[i];
        float other = (dd < 32) ? -xp[i + 32] : xp[i - 32];
        res[i] = v * c + other * s;
    }
    uint2 ho, xo;
    ho.x = pack_h2(res[0], res[1]);
    ho.y = pack_h2(res[2], res[3]);
    xo.x = pack_h2(xv.x, xv.y);
    xo.y = pack_h2(xv.z, xv.w);
    *(uint2*)&hi[base] = ho;
    *(uint2*)&xh[base] = xo;
}

// ---------------- HMMA fp16 GEMM (R13 config): 128x128 CTA, BK=32, 4 stages ------
// RES=1 adds fp32 residual Res[row*N+col] in the epilogue (fp32 add, exact).
#define STG 4
#define GEMM_SMEM (STG * 16384)

template<int ACT, int MODE, int RES>
__global__ __launch_bounds__(256, 2) void gemm_mma_kernel(
    const __half* __restrict__ Ah, const __half* __restrict__ Bh,
    const float* __restrict__ bias, const float* __restrict__ Res,
    float* __restrict__ C, __half* __restrict__ Ch,
    int M, int N, int K)
{
    extern __shared__ __align__(16) char smc[];
    uint32_t sbase = smem_u32(smc);
    const uint32_t BOFF = STG * 8192;

    int t = threadIdx.x;
    int lane = t & 31, wid = t >> 5;
    int warp_m = wid & 3, warp_n = wid >> 2;
    int m0 = blockIdx.y * 128;
    int n0 = blockIdx.x * 128;

    uint32_t aOff[2];
    size_t   aG[2], bG[2];
#pragma unroll
    for (int i = 0; i < 2; i++) {
        int idx = t + i * 256;
        int row = idx >> 2, ch = idx & 3;
        uint32_t swz = (uint32_t)(ch ^ ((row >> 1) & 3));
        aOff[i] = (uint32_t)(row * 64) + swz * 16;
        aG[i] = (size_t)(m0 + row) * K + ch * 8;
        bG[i] = (size_t)(n0 + row) * K + ch * 8;
    }

    uint32_t aRow64[2]; int aRswz[2];
#pragma unroll
    for (int ti = 0; ti < 2; ti++) {
        int row = warp_m * 32 + ti * 16 + (lane & 15);
        aRow64[ti] = (uint32_t)(row * 64);
        aRswz[ti] = (row >> 1) & 3;
    }
    int aChunkBase = lane >> 4;
    uint32_t bRow64[4]; int bRswz[4];
#pragma unroll
    for (int j2 = 0; j2 < 4; j2++) {
        int row = warp_n * 64 + j2 * 16 + ((lane >> 4) << 3) + (lane & 7);
        bRow64[j2] = (uint32_t)(row * 64);
        bRswz[j2] = (row >> 1) & 3;
    }
    int bChunkBase = (lane >> 3) & 1;

    float acc[2][8][4];
#pragma unroll
    for (int mi = 0; mi < 2; mi++)
#pragma unroll
        for (int nj = 0; nj < 8; nj++)
#pragma unroll
            for (int r = 0; r < 4; r++) acc[mi][nj][r] = 0.f;

    int NC = K >> 5;

#pragma unroll
    for (int p = 0; p < 3; p++) {
        size_t ko = (size_t)p * 32;
        uint32_t sa = sbase + (uint32_t)p * 8192;
        uint32_t sb = sbase + BOFF + (uint32_t)p * 8192;
#pragma unroll
        for (int i = 0; i < 2; i++) cp16(sa + aOff[i], Ah + aG[i] + ko);
#pragma unroll
        for (int i = 0; i < 2; i++) cp16(sb + aOff[i], Bh + bG[i] + ko);
        cp_commit();
    }
    cp_wait1();
    __syncthreads();

    uint32_t a0[2][4], b0[4][4];
    uint32_t a1[2][4], b1[4][4];

    {
        uint32_t sa = sbase, sb = sbase + BOFF;
#pragma unroll
        for (int ti = 0; ti < 2; ti++) {
            int ch = aChunkBase;
            ldm_x4(sa + aRow64[ti] + (uint32_t)((ch ^ aRswz[ti]) * 16),
                   a0[ti][0], a0[ti][1], a0[ti][2], a0[ti][3]);
        }
#pragma unroll
        for (int j2 = 0; j2 < 4; j2++) {
            int ch = bChunkBase;
            ldm_x4(sb + bRow64[j2] + (uint32_t)((ch ^ bRswz[j2]) * 16),
                   b0[j2][0], b0[j2][1], b0[j2][2], b0[j2][3]);
        }
    }

    for (int c = 0; c < NC; c++) {
        uint32_t sa = sbase + (uint32_t)(c & (STG - 1)) * 8192;
        uint32_t sb = sbase + BOFF + (uint32_t)(c & (STG - 1)) * 8192;

        if (c + 3 < NC) {
            size_t ko = (size_t)(c + 3) * 32;
            uint32_t st = (uint32_t)((c + 3) & (STG - 1));
            uint32_t sa3 = sbase + st * 8192;
            uint32_t sb3 = sbase + BOFF + st * 8192;
#pragma unroll
            for (int i = 0; i < 2; i++) cp16(sa3 + aOff[i], Ah + aG[i] + ko);
#pragma unroll
            for (int i = 0; i < 2; i++) cp16(sb3 + aOff[i], Bh + bG[i] + ko);
        }
        cp_commit();

#pragma unroll
        for (int ti = 0; ti < 2; ti++) {
            int ch = 2 + aChunkBase;
            ldm_x4(sa + aRow64[ti] + (uint32_t)((ch ^ aRswz[ti]) * 16),
                   a1[ti][0], a1[ti][1], a1[ti][2], a1[ti][3]);
        }
#pragma unroll
        for (int j2 = 0; j2 < 4; j2++) {
            int ch = 2 + bChunkBase;
            ldm_x4(sb + bRow64[j2] + (uint32_t)((ch ^ bRswz[j2]) * 16),
                   b1[j2][0], b1[j2][1], b1[j2][2], b1[j2][3]);
        }

#pragma unroll
        for (int mi = 0; mi < 2; mi++)
#pragma unroll
            for (int nj = 0; nj < 8; nj++)
                mma16816(acc[mi][nj], a0[mi], &b0[nj >> 1][(nj & 1) * 2]);

        if (c + 1 < NC) {
            uint32_t sa2 = sbase + (uint32_t)((c + 1) & (STG - 1)) * 8192;
            uint32_t sb2 = sbase + BOFF + (uint32_t)((c + 1) & (STG - 1)) * 8192;
#pragma unroll
            for (int ti = 0; ti < 2; ti++) {
                int ch = aChunkBase;
                ldm_x4(sa2 + aRow64[ti] + (uint32_t)((ch ^ aRswz[ti]) * 16),
                       a0[ti][0], a0[ti][1], a0[ti][2], a0[ti][3]);
            }
#pragma unroll
            for (int j2 = 0; j2 < 4; j2++) {
                int ch = bChunkBase;
                ldm_x4(sb2 + bRow64[j2] + (uint32_t)((ch ^ bRswz[j2]) * 16),
                       b0[j2][0], b0[j2][1], b0[j2][2], b0[j2][3]);
            }
        }

#pragma unroll
        for (int mi = 0; mi < 2; mi++)
#pragma unroll
            for (int nj = 0; nj < 8; nj++)
                mma16816(acc[mi][nj], a1[mi], &b1[nj >> 1][(nj & 1) * 2]);

        cp_wait1();
        __syncthreads();
    }

    int tq = lane >> 2, tr = lane & 3;
#pragma unroll
    for (int mi = 0; mi < 2; mi++) {
#pragma unroll
        for (int nj = 0; nj < 8; nj++) {
            int row0 = m0 + warp_m * 32 + mi * 16 + tq;
            int col = n0 + warp_n * 64 + nj * 8 + tr * 2;
            float c0 = __ldg(&bias[col]), c1 = __ldg(&bias[col + 1]);
            float v0 = acc[mi][nj][0] + c0, v1 = acc[mi][nj][1] + c1;
            float v2 = acc[mi][nj][2] + c0, v3 = acc[mi][nj][3] + c1;
            if (ACT) {
                v0 = 0.5f * v0 * (1.0f + erff(v0 * 0.70710678118654752f));
                v1 = 0.5f * v1 * (1.0f + erff(v1 * 0.70710678118654752f));
                v2 = 0.5f * v2 * (1.0f + erff(v2 * 0.70710678118654752f));
                v3 = 0.5f * v3 * (1.0f + erff(v3 * 0.70710678118654752f));
            }
            if (RES) {
                float2 r0 = *(const float2*)&Res[(size_t)row0 * N + col];
                float2 r1 = *(const float2*)&Res[(size_t)(row0 + 8) * N + col];
                v0 += r0.x; v1 += r0.y; v2 += r1.x; v3 += r1.y;
            }
            if (MODE == 0) {
                *(float2*)&C[(size_t)row0 * N + col] = make_float2(v0, v1);
                *(float2*)&C[(size_t)(row0 + 8) * N + col] = make_float2(v2, v3);
            } else {
                *(uint32_t*)&Ch[(size_t)row0 * N + col] = pack_h2(v0, v1);
                *(uint32_t*)&Ch[(size_t)(row0 + 8) * N + col] = pack_h2(v2, v3);
            }
        }
    }
}

// ---------------- tensor-core flash attention: 128-q tile, 256 thr ---------------
__global__ __launch_bounds__(256) void attn_mma_kernel(
    const __half* __restrict__ qk,   // [BS][2E] : Q | K
    const __half* __restrict__ v,    // [BS][E]
    __half* __restrict__ ch)         // ctx [BS][E]
{
    __shared__ __align__(16) __half q_s[128 * 64];
    __shared__ __align__(16) __half k_s[64 * 64];
    __shared__ __align__(16) __half v_s[64 * 64];

    int b = blockIdx.z, h = blockIdx.y;
    int q0 = blockIdx.x * 128;
    int t = threadIdx.x;
    int lane = t & 31, w = t >> 5;
    uint32_t sq = smem_u32(q_s), sk = smem_u32(k_s), sv = smem_u32(v_s);

#pragma unroll
    for (int i = 0; i < 4; i++) {
        int idx = t + i * 256;
        int r = idx >> 3, c = idx & 7;
        *(uint4*)((char*)q_s + r * 128 + ((c ^ (r & 7)) * 16)) =
            *(const uint4*)&qk[(size_t)(b * SS + q0 + r) * (2 * E_) + h * HD + c * 8];
    }
    __syncthreads();

    uint32_t qa[4][4];
#pragma unroll
    for (int kc = 0; kc < 4; kc++) {
        int m = lane >> 3;
        int rr = w * 16 + (lane & 7) + ((m & 1) ? 8 : 0);
        int cc = kc * 2 + (m >> 1);
        uint32_t addr = sq + (uint32_t)(rr * 128 + ((cc ^ (rr & 7)) * 16));
        ldm_x4(addr, qa[kc][0], qa[kc][1], qa[kc][2], qa[kc][3]);
    }

    float o[8][4];
#pragma unroll
    for (int d = 0; d < 8; d++)
#pragma unroll
        for (int r = 0; r < 4; r++) o[d][r] = 0.f;
    float mrow[2] = {-1e30f, -1e30f};
    float lsum[2] = {0.f, 0.f};

    int kstart = q0 - WIN; if (kstart < 0) kstart = 0;
    int kend = q0 + 128 + WIN; if (kend > SS) kend = SS;
    const float scale = 0.125f;
    int tq = lane >> 2, tr = lane & 3;

    for (int kb = kstart; kb < kend; kb += 64) {
        __syncthreads();
#pragma unroll
        for (int i = 0; i < 2; i++) {
            int idx = t + i * 256;
            int r = idx >> 3, c = idx & 7;
            uint32_t so = (uint32_t)(r * 128 + ((c ^ (r & 7)) * 16));
            *(uint4*)((char*)k_s + so) =
                *(const uint4*)&qk[(size_t)(b * SS + kb + r) * (2 * E_) + E_ + h * HD + c * 8];
            *(uint4*)((char*)v_s + so) =
                *(const uint4*)&v[(size_t)(b * SS + kb + r) * E_ + h * HD + c * 8];
        }
        __syncthreads();

        float s[8][4];
#pragma unroll
        for (int j = 0; j < 8; j++)
#pragma unroll
            for (int r = 0; r < 4; r++) s[j][r] = 0.f;
#pragma unroll
        for (int kc = 0; kc < 4; kc++) {
#pragma unroll
            for (int j2 = 0; j2 < 4; j2++) {
                int m = lane >> 3;
                int rr = j2 * 16 + (lane & 7) + ((m >= 2) ? 8 : 0);
                int cc = kc * 2 + (m & 1);
                uint32_t addr = sk + (uint32_t)(rr * 128 + ((cc ^ (rr & 7)) * 16));
                uint32_t b0, b1, b2, b3;
                ldm_x4(addr, b0, b1, b2, b3);
                uint32_t bj[2] = {b0, b1}, bj1[2] = {b2, b3};
                mma16816(s[2 * j2],     qa[kc], bj);
                mma16816(s[2 * j2 + 1], qa[kc], bj1);
            }
        }

#pragma unroll
        for (int e = 0; e < 2; e++) {
            int qi = q0 + w * 16 + tq + e * 8;
            float rmax = -1e30f;
#pragma unroll
            for (int j = 0; j < 8; j++) {
#pragma unroll
                for (int u = 0; u < 2; u++) {
                    int col = kb + j * 8 + tr * 2 + u;
                    int diff = qi - col;
                    bool ok = (diff <= WIN) && (diff >= -WIN);
                    float val = ok ? s[j][e * 2 + u] * scale : -1e30f;
                    s[j][e * 2 + u] = val;
                    rmax = fmaxf(rmax, val);
                }
            }
            rmax = fmaxf(rmax, __shfl_xor_sync(0xffffffffu, rmax, 1));
            rmax = fmaxf(rmax, __shfl_xor_sync(0xffffffffu, rmax, 2));
            float mnew = fmaxf(mrow[e], rmax);
            float corr = __expf(mrow[e] - mnew);
            float rsum = 0.f;
#pragma unroll
            for (int j = 0; j < 8; j++) {
#pragma unroll
                for (int u = 0; u < 2; u++) {
                    float p = __expf(s[j][e * 2 + u] - mnew);
                    s[j][e * 2 + u] = p;
                    rsum += p;
                }
            }
            rsum += __shfl_xor_sync(0xffffffffu, rsum, 1);
            rsum += __shfl_xor_sync(0xffffffffu, rsum, 2);
            mrow[e] = mnew;
            lsum[e] = lsum[e] * corr + rsum;
#pragma unroll
            for (int d = 0; d < 8; d++) {
                o[d][e * 2] *= corr;
                o[d][e * 2 + 1] *= corr;
            }
        }

#pragma unroll
        for (int kc = 0; kc < 4; kc++) {
            uint32_t pa[4];
            pa[0] = pack_h2(s[2 * kc][0],     s[2 * kc][1]);
            pa[1] = pack_h2(s[2 * kc][2],     s[2 * kc][3]);
            pa[2] = pack_h2(s[2 * kc + 1][0], s[2 * kc + 1][1]);
            pa[3] = pack_h2(s[2 * kc + 1][2], s[2 * kc + 1][3]);
#pragma unroll
            for (int d2 = 0; d2 < 4; d2++) {
                int m = lane >> 3;
                int rr = kc * 16 + (lane & 7) + ((m & 1) ? 8 : 0);
                int cc = 2 * d2 + (m >> 1);
                uint32_t addr = sv + (uint32_t)(rr * 128 + ((cc ^ (rr & 7)) * 16));
                uint32_t b0, b1, b2, b3;
                ldm_x4t(addr, b0, b1, b2, b3);
                uint32_t bd[2] = {b0, b1}, bd1[2] = {b2, b3};
                mma16816(o[2 * d2],     pa, bd);
                mma16816(o[2 * d2 + 1], pa, bd1);
            }
        }
    }

    float inv0 = 1.f / lsum[0], inv1 = 1.f / lsum[1];
#pragma unroll
    for (int d = 0; d < 8; d++) {
        int row0 = q0 + w * 16 + tq;
        int col = h * HD + d * 8 + tr * 2;
        *(uint32_t*)&ch[(size_t)(b * SS + row0) * E_ + col] =
            pack_h2(o[d][0] * inv0, o[d][1] * inv0);
        *(uint32_t*)&ch[(size_t)(b * SS + row0 + 8) * E_ + col] =
            pack_h2(o[d][2] * inv1, o[d][3] * inv1);
    }
}

// ---------------- LayerNorm (single input; optional fused fp16 out) --------------
__global__ __launch_bounds__(256) void ln_kernel(
    const float* __restrict__ a,
    const float* __restrict__ g, const float* __restrict__ be,
    float* __restrict__ out, __half* __restrict__ oh)
{
    int row = blockIdx.x;
    int t = threadIdx.x;
    size_t base = (size_t)row * E_;
    float4 av = *(const float4*)&a[base + t * 4];
    float v0 = av.x, v1 = av.y, v2 = av.z, v3 = av.w;
    float sum = v0 + v1 + v2 + v3;
    float sq = v0 * v0 + v1 * v1 + v2 * v2 + v3 * v3;
#pragma unroll
    for (int off = 16; off; off >>= 1) {
        sum += __shfl_xor_sync(0xffffffffu, sum, off);
        sq  += __shfl_xor_sync(0xffffffffu, sq, off);
    }
    __shared__ float ss[8], sq2[8], stat[2];
    int w = t >> 5;
    if ((t & 31) == 0) { ss[w] = sum; sq2[w] = sq; }
    __syncthreads();
    if (t == 0) {
        float S1 = 0.f, S2 = 0.f;
        for (int i = 0; i < 8; i++) { S1 += ss[i]; S2 += sq2[i]; }
        float mean = S1 * (1.0f / E_);
        float var = S2 * (1.0f / E_) - mean * mean;
        stat[0] = mean;
        stat[1] = rsqrtf(var + 1e-5f);
    }
    __syncthreads();
    float mean = stat[0], rstd = stat[1];
    float4 gv = *(const float4*)&g[t * 4];
    float4 bv = *(const float4*)&be[t * 4];
    float o[4];
    o[0] = (v0 - mean) * rstd * gv.x + bv.x;
    o[1] = (v1 - mean) * rstd * gv.y + bv.y;
    o[2] = (v2 - mean) * rstd * gv.z + bv.z;
    o[3] = (v3 - mean) * rstd * gv.w + bv.w;
    *(float4*)&out[base + t * 4] = make_float4(o[0], o[1], o[2], o[3]);
    if (oh) {
        uint2 ho;
        ho.x = pack_h2(o[0], o[1]);
        ho.y = pack_h2(o[2], o[3]);
        *(uint2*)&oh[base + t * 4] = ho;
    }
}

// ---------------- launch ---------------------------------------------------------
extern "C" void kernel_launch(void* const* d_in, const int* in_sizes, int n_in,
                              void* d_out, int out_size)
{
    (void)in_sizes; (void)n_in; (void)out_size;
    const float* x    = (const float*)d_in[0];
    const float* ipw  = (const float*)d_in[1];
    const float* ipb  = (const float*)d_in[2];
    const float* opw  = (const float*)d_in[3];
    const float* opb  = (const float*)d_in[4];
    const float* ln1g = (const float*)d_in[5];
    const float* ln1b = (const float*)d_in[6];
    const float* w1   = (const float*)d_in[7];
    const float* b1   = (const float*)d_in[8];
    const float* w2   = (const float*)d_in[9];
    const float* b2   = (const float*)d_in[10];
    const float* ln2g = (const float*)d_in[11];
    const float* ln2b = (const float*)d_in[12];
    float* out = (float*)d_out;

    float *tmp, *x1;
    cudaGetSymbolAddress((void**)&tmp, g_tmp);
    cudaGetSymbolAddress((void**)&x1,  g_x1);

    __half *a1h, *a2h, *x1h, *hh, *qkh, *vh, *wih, *woh, *w1h, *w2h;
    cudaGetSymbolAddress((void**)&a1h, g_a1h);
    cudaGetSymbolAddress((void**)&a2h, g_a2h);
    cudaGetSymbolAddress((void**)&x1h, g_x1h);
    cudaGetSymbolAddress((void**)&hh,  g_hh);
    cudaGetSymbolAddress((void**)&qkh, g_qkh);
    cudaGetSymbolAddress((void**)&vh,  g_vh);
    cudaGetSymbolAddress((void**)&wih, g_wih); cudaGetSymbolAddress((void**)&woh, g_woh);
    cudaGetSymbolAddress((void**)&w1h, g_w1h); cudaGetSymbolAddress((void**)&w2h, g_w2h);

    cudaFuncSetAttribute(gemm_mma_kernel<0,0,1>,
                         cudaFuncAttributeMaxDynamicSharedMemorySize, GEMM_SMEM);
    cudaFuncSetAttribute(gemm_mma_kernel<0,1,0>,
                         cudaFuncAttributeMaxDynamicSharedMemorySize, GEMM_SMEM);
    cudaFuncSetAttribute(gemm_mma_kernel<1,1,0>,
                         cudaFuncAttributeMaxDynamicSharedMemorySize, GEMM_SMEM);

    cudaStream_t s0 = 0, s2 = g_sp.s2;

    cudaEventRecord(g_sp.eStart, s0);
    cudaStreamWaitEvent(s2, g_sp.eStart, 0);

    // 0: RoPE(x) -> a1h, fp16 x -> a2h   (s0)
    rope_conv_kernel<<<BS, 256, 0, s0>>>(x, a1h, a2h);
    cudaEventRecord(g_sp.eR, s0);

    // 1: in_proj weight conv (s2)
    conv_kernel<<<(3 * E_ * E_) / 1024, 256, 0, s2>>>(ipw, wih);
    cudaEventRecord(g_sp.eWih, s2);

    // 2: fused Q|K GEMM (s0)
    cudaStreamWaitEvent(s0, g_sp.eWih, 0);
    gemm_mma_kernel<0,1,0><<<dim3(16, 64), 256, GEMM_SMEM, s0>>>(
        a1h, wih, ipb, nullptr, nullptr, qkh, BS, 2 * E_, E_);

    // 3: V GEMM (s2)
    cudaStreamWaitEvent(s2, g_sp.eR, 0);
    gemm_mma_kernel<0,1,0><<<dim3(8, 64), 256, GEMM_SMEM, s2>>>(
        a2h, wih + (size_t)2*E_*E_, ipb + 2 * E_, nullptr, nullptr, vh, BS, E_, E_);
    cudaEventRecord(g_sp.eV, s2);

    // 4: out_proj weight conv (s2)
    conv_kernel<<<(E_ * E_) / 1024, 256, 0, s2>>>(opw, woh);

    // 5: attention (s0) -> ctx into a2h
    cudaStreamWaitEvent(s0, g_sp.eV, 0);
    attn_mma_kernel<<<dim3(SS / 128, NH, BB), 256, 0, s0>>>(qkh, vh, a2h);

    // 6,7: FFN weight convs (s2)
    conv_kernel<<<(FF * E_) / 1024, 256, 0, s2>>>(w1, w1h);
    conv_kernel<<<(FF * E_) / 1024, 256, 0, s2>>>(w2, w2h);
    cudaEventRecord(g_sp.eW2, s2);

    cudaStreamWaitEvent(s0, g_sp.eW2, 0);

    // 8: out-proj GEMM (+residual x fused); 9: LN1
    gemm_mma_kernel<0,0,1><<<dim3(8, 64), 256, GEMM_SMEM, s0>>>(
        a2h, woh, opb, x, tmp, nullptr, BS, E_, E_);
    ln_kernel<<<BS, 256, 0, s0>>>(tmp, ln1g, ln1b, x1, x1h);

    // 10-12: FFN (+residual x1 fused in ffn2) + LN2
    gemm_mma_kernel<1,1,0><<<dim3(32, 64), 256, GEMM_SMEM, s0>>>(
        x1h, w1h, b1, nullptr, nullptr, hh, BS, FF, E_);
    gemm_mma_kernel<0,0,1><<<dim3(8, 64), 256, GEMM_SMEM, s0>>>(
        hh, w2h, b2, x1, tmp, nullptr, BS, E_, FF);
    ln_kernel<<<BS, 256, 0, s0>>>(tmp, ln2g, ln2b, out, nullptr);
}

// round 17
// speedup vs baseline: 1.1484x; 1.0146x over previous
#include <cuda_runtime.h>
#include <cuda_fp16.h>
#include <math.h>
#include <stdint.h>

#define E_   1024
#define NH   16
#define HD   64
#define WIN  256
#define BB   8
#define SS   1024
#define BS   (BB*SS)
#define FF   4096

// ---------------- scratch ------------------------------------------------------
__device__ float g_tmp[BS*E_];
__device__ float g_x1[BS*E_];

__device__ __half g_a1h[BS*E_];
__device__ __half g_a2h[BS*E_];
__device__ __half g_x1h[BS*E_];
__device__ __half g_hh[(size_t)BS*FF];
__device__ __half g_qkh[(size_t)BS*2*E_];
__device__ __half g_vh[BS*E_];
__device__ __half g_wih[3*E_*E_];
__device__ __half g_woh[E_*E_];
__device__ __half g_w1h[FF*E_];
__device__ __half g_w2h[FF*E_];

// ---------------- streams/events -------------------------------------------------
struct StreamPack {
    cudaStream_t s2;
    cudaEvent_t eStart, eR, eWih, eV, eW2;
    StreamPack() {
        cudaStreamCreateWithFlags(&s2, cudaStreamNonBlocking);
        cudaEventCreateWithFlags(&eStart, cudaEventDisableTiming);
        cudaEventCreateWithFlags(&eR,     cudaEventDisableTiming);
        cudaEventCreateWithFlags(&eWih,   cudaEventDisableTiming);
        cudaEventCreateWithFlags(&eV,     cudaEventDisableTiming);
        cudaEventCreateWithFlags(&eW2,    cudaEventDisableTiming);
    }
};
static StreamPack g_sp;

// ---------------- helpers -------------------------------------------------------
__device__ __forceinline__ uint32_t smem_u32(const void* p) {
    uint32_t a;
    asm("{ .reg .u64 t; cvta.to.shared.u64 t, %1; cvt.u32.u64 %0, t; }" : "=r"(a) : "l"(p));
    return a;
}
__device__ __forceinline__ void cp16(uint32_t dst, const void* src) {
    asm volatile("cp.async.cg.shared.global [%0], [%1], 16;" :: "r"(dst), "l"(src));
}
__device__ __forceinline__ void cp_commit() { asm volatile("cp.async.commit_group;"); }
__device__ __forceinline__ void cp_wait1()  { asm volatile("cp.async.wait_group 1;" ::: "memory"); }
__device__ __forceinline__ void ldm_x4(uint32_t addr, uint32_t& r0, uint32_t& r1,
                                       uint32_t& r2, uint32_t& r3) {
    asm volatile("ldmatrix.sync.aligned.m8n8.x4.shared.b16 {%0,%1,%2,%3}, [%4];"
                 : "=r"(r0), "=r"(r1), "=r"(r2), "=r"(r3) : "r"(addr));
}
__device__ __forceinline__ void ldm_x4t(uint32_t addr, uint32_t& r0, uint32_t& r1,
                                        uint32_t& r2, uint32_t& r3) {
    asm volatile("ldmatrix.sync.aligned.m8n8.x4.trans.shared.b16 {%0,%1,%2,%3}, [%4];"
                 : "=r"(r0), "=r"(r1), "=r"(r2), "=r"(r3) : "r"(addr));
}
__device__ __forceinline__ void mma16816(float* c, const uint32_t* a, const uint32_t* b) {
    asm volatile(
        "mma.sync.aligned.m16n8k16.row.col.f32.f16.f16.f32 "
        "{%0,%1,%2,%3}, {%4,%5,%6,%7}, {%8,%9}, {%0,%1,%2,%3};"
        : "+f"(c[0]), "+f"(c[1]), "+f"(c[2]), "+f"(c[3])
        : "r"(a[0]), "r"(a[1]), "r"(a[2]), "r"(a[3]), "r"(b[0]), "r"(b[1]));
}
__device__ __forceinline__ uint32_t pack_h2(float a, float b) {
    __half2 h = __floats2half2_rn(a, b);
    return *(uint32_t*)&h;
}

// ---------------- convert fp32 -> fp16 -------------------------------------------
__global__ __launch_bounds__(256) void conv_kernel(const float* __restrict__ src,
                                                   __half* __restrict__ hi)
{
    size_t i = ((size_t)blockIdx.x * 256 + threadIdx.x) * 4;
    float4 v = *(const float4*)&src[i];
    uint2 ho;
    ho.x = pack_h2(v.x, v.y);
    ho.y = pack_h2(v.z, v.w);
    *(uint2*)&hi[i] = ho;
}

// ---------------- RoPE on raw x -> fp16 roped + fp16 plain -----------------------
__global__ __launch_bounds__(256) void rope_conv_kernel(const float* __restrict__ x,
                                                        __half* __restrict__ hi,
                                                        __half* __restrict__ xh)
{
    int tok = blockIdx.x;
    float pos = (float)(tok & (SS - 1));
    int base = tok * E_ + threadIdx.x * 4;
    int d = (threadIdx.x * 4) & (HD - 1);
    const float* xp = &x[base];
    float4 xv = *(const float4*)xp;
    float res[4];
    const float LOG2_10000 = 13.287712379549449f;
#pragma unroll
    for (int i = 0; i < 4; i++) {
        int dd = d + i;
        int j = (dd < 32) ? dd : dd - 32;
        float fr = exp2f(-(float)j * (2.0f / 64.0f) * LOG2_10000);
        float ang = pos * fr;
        float s, c;
        sincosf(ang, &s, &c);
        float v = ((const float*)&xv)[i];
        float other = (dd < 32) ? -xp[i + 32] : xp[i - 32];
        res[i] = v * c + other * s;
    }
    uint2 ho, xo;
    ho.x = pack_h2(res[0], res[1]);
    ho.y = pack_h2(res[2], res[3]);
    xo.x = pack_h2(xv.x, xv.y);
    xo.y = pack_h2(xv.z, xv.w);
    *(uint2*)&hi[base] = ho;
    *(uint2*)&xh[base] = xo;
}

// ---------------- HMMA fp16 GEMM (R13 config): 128x128 CTA, BK=32, 4 stages ------
#define STG 4
#define GEMM_SMEM (STG * 16384)

template<int ACT, int MODE, int RES>
__global__ __launch_bounds__(256, 2) void gemm_mma_kernel(
    const __half* __restrict__ Ah, const __half* __restrict__ Bh,
    const float* __restrict__ bias, const float* __restrict__ Res,
    float* __restrict__ C, __half* __restrict__ Ch,
    int M, int N, int K)
{
    extern __shared__ __align__(16) char smc[];
    uint32_t sbase = smem_u32(smc);
    const uint32_t BOFF = STG * 8192;

    int t = threadIdx.x;
    int lane = t & 31, wid = t >> 5;
    int warp_m = wid & 3, warp_n = wid >> 2;
    int m0 = blockIdx.y * 128;
    int n0 = blockIdx.x * 128;

    uint32_t aOff[2];
    size_t   aG[2], bG[2];
#pragma unroll
    for (int i = 0; i < 2; i++) {
        int idx = t + i * 256;
        int row = idx >> 2, ch = idx & 3;
        uint32_t swz = (uint32_t)(ch ^ ((row >> 1) & 3));
        aOff[i] = (uint32_t)(row * 64) + swz * 16;
        aG[i] = (size_t)(m0 + row) * K + ch * 8;
        bG[i] = (size_t)(n0 + row) * K + ch * 8;
    }

    uint32_t aRow64[2]; int aRswz[2];
#pragma unroll
    for (int ti = 0; ti < 2; ti++) {
        int row = warp_m * 32 + ti * 16 + (lane & 15);
        aRow64[ti] = (uint32_t)(row * 64);
        aRswz[ti] = (row >> 1) & 3;
    }
    int aChunkBase = lane >> 4;
    uint32_t bRow64[4]; int bRswz[4];
#pragma unroll
    for (int j2 = 0; j2 < 4; j2++) {
        int row = warp_n * 64 + j2 * 16 + ((lane >> 4) << 3) + (lane & 7);
        bRow64[j2] = (uint32_t)(row * 64);
        bRswz[j2] = (row >> 1) & 3;
    }
    int bChunkBase = (lane >> 3) & 1;

    float acc[2][8][4];
#pragma unroll
    for (int mi = 0; mi < 2; mi++)
#pragma unroll
        for (int nj = 0; nj < 8; nj++)
#pragma unroll
            for (int r = 0; r < 4; r++) acc[mi][nj][r] = 0.f;

    int NC = K >> 5;

#pragma unroll
    for (int p = 0; p < 3; p++) {
        size_t ko = (size_t)p * 32;
        uint32_t sa = sbase + (uint32_t)p * 8192;
        uint32_t sb = sbase + BOFF + (uint32_t)p * 8192;
#pragma unroll
        for (int i = 0; i < 2; i++) cp16(sa + aOff[i], Ah + aG[i] + ko);
#pragma unroll
        for (int i = 0; i < 2; i++) cp16(sb + aOff[i], Bh + bG[i] + ko);
        cp_commit();
    }
    cp_wait1();
    __syncthreads();

    uint32_t a0[2][4], b0[4][4];
    uint32_t a1[2][4], b1[4][4];

    {
        uint32_t sa = sbase, sb = sbase + BOFF;
#pragma unroll
        for (int ti = 0; ti < 2; ti++) {
            int ch = aChunkBase;
            ldm_x4(sa + aRow64[ti] + (uint32_t)((ch ^ aRswz[ti]) * 16),
                   a0[ti][0], a0[ti][1], a0[ti][2], a0[ti][3]);
        }
#pragma unroll
        for (int j2 = 0; j2 < 4; j2++) {
            int ch = bChunkBase;
            ldm_x4(sb + bRow64[j2] + (uint32_t)((ch ^ bRswz[j2]) * 16),
                   b0[j2][0], b0[j2][1], b0[j2][2], b0[j2][3]);
        }
    }

    for (int c = 0; c < NC; c++) {
        uint32_t sa = sbase + (uint32_t)(c & (STG - 1)) * 8192;
        uint32_t sb = sbase + BOFF + (uint32_t)(c & (STG - 1)) * 8192;

        if (c + 3 < NC) {
            size_t ko = (size_t)(c + 3) * 32;
            uint32_t st = (uint32_t)((c + 3) & (STG - 1));
            uint32_t sa3 = sbase + st * 8192;
            uint32_t sb3 = sbase + BOFF + st * 8192;
#pragma unroll
            for (int i = 0; i < 2; i++) cp16(sa3 + aOff[i], Ah + aG[i] + ko);
#pragma unroll
            for (int i = 0; i < 2; i++) cp16(sb3 + aOff[i], Bh + bG[i] + ko);
        }
        cp_commit();

#pragma unroll
        for (int ti = 0; ti < 2; ti++) {
            int ch = 2 + aChunkBase;
            ldm_x4(sa + aRow64[ti] + (uint32_t)((ch ^ aRswz[ti]) * 16),
                   a1[ti][0], a1[ti][1], a1[ti][2], a1[ti][3]);
        }
#pragma unroll
        for (int j2 = 0; j2 < 4; j2++) {
            int ch = 2 + bChunkBase;
            ldm_x4(sb + bRow64[j2] + (uint32_t)((ch ^ bRswz[j2]) * 16),
                   b1[j2][0], b1[j2][1], b1[j2][2], b1[j2][3]);
        }

#pragma unroll
        for (int mi = 0; mi < 2; mi++)
#pragma unroll
            for (int nj = 0; nj < 8; nj++)
                mma16816(acc[mi][nj], a0[mi], &b0[nj >> 1][(nj & 1) * 2]);

        if (c + 1 < NC) {
            uint32_t sa2 = sbase + (uint32_t)((c + 1) & (STG - 1)) * 8192;
            uint32_t sb2 = sbase + BOFF + (uint32_t)((c + 1) & (STG - 1)) * 8192;
#pragma unroll
            for (int ti = 0; ti < 2; ti++) {
                int ch = aChunkBase;
                ldm_x4(sa2 + aRow64[ti] + (uint32_t)((ch ^ aRswz[ti]) * 16),
                       a0[ti][0], a0[ti][1], a0[ti][2], a0[ti][3]);
            }
#pragma unroll
            for (int j2 = 0; j2 < 4; j2++) {
                int ch = bChunkBase;
                ldm_x4(sb2 + bRow64[j2] + (uint32_t)((ch ^ bRswz[j2]) * 16),
                       b0[j2][0], b0[j2][1], b0[j2][2], b0[j2][3]);
            }
        }

#pragma unroll
        for (int mi = 0; mi < 2; mi++)
#pragma unroll
            for (int nj = 0; nj < 8; nj++)
                mma16816(acc[mi][nj], a1[mi], &b1[nj >> 1][(nj & 1) * 2]);

        cp_wait1();
        __syncthreads();
    }

    int tq = lane >> 2, tr = lane & 3;
#pragma unroll
    for (int mi = 0; mi < 2; mi++) {
#pragma unroll
        for (int nj = 0; nj < 8; nj++) {
            int row0 = m0 + warp_m * 32 + mi * 16 + tq;
            int col = n0 + warp_n * 64 + nj * 8 + tr * 2;
            float c0 = __ldg(&bias[col]), c1 = __ldg(&bias[col + 1]);
            float v0 = acc[mi][nj][0] + c0, v1 = acc[mi][nj][1] + c1;
            float v2 = acc[mi][nj][2] + c0, v3 = acc[mi][nj][3] + c1;
            if (ACT) {
                v0 = 0.5f * v0 * (1.0f + erff(v0 * 0.70710678118654752f));
                v1 = 0.5f * v1 * (1.0f + erff(v1 * 0.70710678118654752f));
                v2 = 0.5f * v2 * (1.0f + erff(v2 * 0.70710678118654752f));
                v3 = 0.5f * v3 * (1.0f + erff(v3 * 0.70710678118654752f));
            }
            if (RES) {
                float2 r0 = *(const float2*)&Res[(size_t)row0 * N + col];
                float2 r1 = *(const float2*)&Res[(size_t)(row0 + 8) * N + col];
                v0 += r0.x; v1 += r0.y; v2 += r1.x; v3 += r1.y;
            }
            if (MODE == 0) {
                *(float2*)&C[(size_t)row0 * N + col] = make_float2(v0, v1);
                *(float2*)&C[(size_t)(row0 + 8) * N + col] = make_float2(v2, v3);
            } else {
                *(uint32_t*)&Ch[(size_t)row0 * N + col] = pack_h2(v0, v1);
                *(uint32_t*)&Ch[(size_t)(row0 + 8) * N + col] = pack_h2(v2, v3);
            }
        }
    }
}

// ---------------- tensor-core flash attention: 128-q tile, cp.async K/V pipeline --
// dyn smem: Q @0 (16KB), K stages @16384+st*8192, V stages @32768+st*8192 = 48KB
#define ATTN_SMEM 49152

__global__ __launch_bounds__(256) void attn_mma_kernel(
    const __half* __restrict__ qk,   // [BS][2E] : Q | K
    const __half* __restrict__ v,    // [BS][E]
    __half* __restrict__ ch)         // ctx [BS][E]
{
    extern __shared__ __align__(16) char sma[];
    uint32_t sq = smem_u32(sma);
    uint32_t skb = sq + 16384;
    uint32_t svb = sq + 32768;

    int b = blockIdx.z, h = blockIdx.y;
    int q0 = blockIdx.x * 128;
    int t = threadIdx.x;
    int lane = t & 31, w = t >> 5;

    int kstart = q0 - WIN; if (kstart < 0) kstart = 0;
    int kend = q0 + 128 + WIN; if (kend > SS) kend = SS;
    int NB = (kend - kstart) >> 6;

    // K/V loader mapping: 64 rows x 128B per tile, 2 x 16B chunks per thread each
    uint32_t kvOff[2]; size_t kG[2], vG[2];
#pragma unroll
    for (int i = 0; i < 2; i++) {
        int idx = t + i * 256;
        int r = idx >> 3, c = idx & 7;
        kvOff[i] = (uint32_t)(r * 128) + (uint32_t)((c ^ (r & 7)) * 16);
        kG[i] = (size_t)(b * SS + r) * (2 * E_) + E_ + h * HD + c * 8;
        vG[i] = (size_t)(b * SS + r) * E_ + h * HD + c * 8;
    }

    // prologue: issue K/V block 0 into stage 0
    {
        size_t ro = (size_t)kstart * (2 * E_);
        size_t rv = (size_t)kstart * E_;
#pragma unroll
        for (int i = 0; i < 2; i++) {
            cp16(skb + kvOff[i], qk + kG[i] + ro);
            cp16(svb + kvOff[i], v + vG[i] + rv);
        }
        cp_commit();
    }

    // load Q tile (plain stores; overlaps with cp.async above)
#pragma unroll
    for (int i = 0; i < 4; i++) {
        int idx = t + i * 256;
        int r = idx >> 3, c = idx & 7;
        *(uint4*)((char*)sma + r * 128 + ((c ^ (r & 7)) * 16)) =
            *(const uint4*)&qk[(size_t)(b * SS + q0 + r) * (2 * E_) + h * HD + c * 8];
    }
    __syncthreads();

    uint32_t qa[4][4];
#pragma unroll
    for (int kc = 0; kc < 4; kc++) {
        int m = lane >> 3;
        int rr = w * 16 + (lane & 7) + ((m & 1) ? 8 : 0);
        int cc = kc * 2 + (m >> 1);
        uint32_t addr = sq + (uint32_t)(rr * 128 + ((cc ^ (rr & 7)) * 16));
        ldm_x4(addr, qa[kc][0], qa[kc][1], qa[kc][2], qa[kc][3]);
    }

    float o[8][4];
#pragma unroll
    for (int d = 0; d < 8; d++)
#pragma unroll
        for (int r = 0; r < 4; r++) o[d][r] = 0.f;
    float mrow[2] = {-1e30f, -1e30f};
    float lsum[2] = {0.f, 0.f};

    const float scale = 0.125f;
    int tq = lane >> 2, tr = lane & 3;

    for (int ib = 0; ib < NB; ib++) {
        int kb = kstart + ib * 64;
        uint32_t st = (uint32_t)(ib & 1);

        // issue next K/V block into the other stage
        if (ib + 1 < NB) {
            size_t ro = (size_t)(kb + 64) * (2 * E_);
            size_t rv = (size_t)(kb + 64) * E_;
            uint32_t sk2 = skb + (st ^ 1u) * 8192;
            uint32_t sv2 = svb + (st ^ 1u) * 8192;
#pragma unroll
            for (int i = 0; i < 2; i++) {
                cp16(sk2 + kvOff[i], qk + kG[i] + ro);
                cp16(sv2 + kvOff[i], v + vG[i] + rv);
            }
        }
        cp_commit();
        cp_wait1();          // block ib complete (this thread)
        __syncthreads();     // ... visible to all

        uint32_t sk = skb + st * 8192;
        uint32_t sv = svb + st * 8192;

        float s[8][4];
#pragma unroll
        for (int j = 0; j < 8; j++)
#pragma unroll
            for (int r = 0; r < 4; r++) s[j][r] = 0.f;
#pragma unroll
        for (int kc = 0; kc < 4; kc++) {
#pragma unroll
            for (int j2 = 0; j2 < 4; j2++) {
                int m = lane >> 3;
                int rr = j2 * 16 + (lane & 7) + ((m >= 2) ? 8 : 0);
                int cc = kc * 2 + (m & 1);
                uint32_t addr = sk + (uint32_t)(rr * 128 + ((cc ^ (rr & 7)) * 16));
                uint32_t b0, b1, b2, b3;
                ldm_x4(addr, b0, b1, b2, b3);
                uint32_t bj[2] = {b0, b1}, bj1[2] = {b2, b3};
                mma16816(s[2 * j2],     qa[kc], bj);
                mma16816(s[2 * j2 + 1], qa[kc], bj1);
            }
        }

#pragma unroll
        for (int e = 0; e < 2; e++) {
            int qi = q0 + w * 16 + tq + e * 8;
            float rmax = -1e30f;
#pragma unroll
            for (int j = 0; j < 8; j++) {
#pragma unroll
                for (int u = 0; u < 2; u++) {
                    int col = kb + j * 8 + tr * 2 + u;
                    int diff = qi - col;
                    bool ok = (diff <= WIN) && (diff >= -WIN);
                    float val = ok ? s[j][e * 2 + u] * scale : -1e30f;
                    s[j][e * 2 + u] = val;
                    rmax = fmaxf(rmax, val);
                }
            }
            rmax = fmaxf(rmax, __shfl_xor_sync(0xffffffffu, rmax, 1));
            rmax = fmaxf(rmax, __shfl_xor_sync(0xffffffffu, rmax, 2));
            float mnew = fmaxf(mrow[e], rmax);
            float corr = __expf(mrow[e] - mnew);
            float rsum = 0.f;
#pragma unroll
            for (int j = 0; j < 8; j++) {
#pragma unroll
                for (int u = 0; u < 2; u++) {
                    float p = __expf(s[j][e * 2 + u] - mnew);
                    s[j][e * 2 + u] = p;
                    rsum += p;
                }
            }
            rsum += __shfl_xor_sync(0xffffffffu, rsum, 1);
            rsum += __shfl_xor_sync(0xffffffffu, rsum, 2);
            mrow[e] = mnew;
            lsum[e] = lsum[e] * corr + rsum;
#pragma unroll
            for (int d = 0; d < 8; d++) {
                o[d][e * 2] *= corr;
                o[d][e * 2 + 1] *= corr;
            }
        }

#pragma unroll
        for (int kc = 0; kc < 4; kc++) {
            uint32_t pa[4];
            pa[0] = pack_h2(s[2 * kc][0],     s[2 * kc][1]);
            pa[1] = pack_h2(s[2 * kc][2],     s[2 * kc][3]);
            pa[2] = pack_h2(s[2 * kc + 1][0], s[2 * kc + 1][1]);
            pa[3] = pack_h2(s[2 * kc + 1][2], s[2 * kc + 1][3]);
#pragma unroll
            for (int d2 = 0; d2 < 4; d2++) {
                int m = lane >> 3;
                int rr = kc * 16 + (lane & 7) + ((m & 1) ? 8 : 0);
                int cc = 2 * d2 + (m >> 1);
                uint32_t addr = sv + (uint32_t)(rr * 128 + ((cc ^ (rr & 7)) * 16));
                uint32_t b0, b1, b2, b3;
                ldm_x4t(addr, b0, b1, b2, b3);
                uint32_t bd[2] = {b0, b1}, bd1[2] = {b2, b3};
                mma16816(o[2 * d2],     pa, bd);
                mma16816(o[2 * d2 + 1], pa, bd1);
            }
        }

        // reads of stage st done — safe for iteration ib+1 to overwrite it
        __syncthreads();
    }

    float inv0 = 1.f / lsum[0], inv1 = 1.f / lsum[1];
#pragma unroll
    for (int d = 0; d < 8; d++) {
        int row0 = q0 + w * 16 + tq;
        int col = h * HD + d * 8 + tr * 2;
        *(uint32_t*)&ch[(size_t)(b * SS + row0) * E_ + col] =
            pack_h2(o[d][0] * inv0, o[d][1] * inv0);
        *(uint32_t*)&ch[(size_t)(b * SS + row0 + 8) * E_ + col] =
            pack_h2(o[d][2] * inv1, o[d][3] * inv1);
    }
}

// ---------------- LayerNorm (single input; optional fused fp16 out) --------------
__global__ __launch_bounds__(256) void ln_kernel(
    const float* __restrict__ a,
    const float* __restrict__ g, const float* __restrict__ be,
    float* __restrict__ out, __half* __restrict__ oh)
{
    int row = blockIdx.x;
    int t = threadIdx.x;
    size_t base = (size_t)row * E_;
    float4 av = *(const float4*)&a[base + t * 4];
    float v0 = av.x, v1 = av.y, v2 = av.z, v3 = av.w;
    float sum = v0 + v1 + v2 + v3;
    float sq = v0 * v0 + v1 * v1 + v2 * v2 + v3 * v3;
#pragma unroll
    for (int off = 16; off; off >>= 1) {
        sum += __shfl_xor_sync(0xffffffffu, sum, off);
        sq  += __shfl_xor_sync(0xffffffffu, sq, off);
    }
    __shared__ float ss[8], sq2[8], stat[2];
    int w = t >> 5;
    if ((t & 31) == 0) { ss[w] = sum; sq2[w] = sq; }
    __syncthreads();
    if (t == 0) {
        float S1 = 0.f, S2 = 0.f;
        for (int i = 0; i < 8; i++) { S1 += ss[i]; S2 += sq2[i]; }
        float mean = S1 * (1.0f / E_);
        float var = S2 * (1.0f / E_) - mean * mean;
        stat[0] = mean;
        stat[1] = rsqrtf(var + 1e-5f);
    }
    __syncthreads();
    float mean = stat[0], rstd = stat[1];
    float4 gv = *(const float4*)&g[t * 4];
    float4 bv = *(const float4*)&be[t * 4];
    float o[4];
    o[0] = (v0 - mean) * rstd * gv.x + bv.x;
    o[1] = (v1 - mean) * rstd * gv.y + bv.y;
    o[2] = (v2 - mean) * rstd * gv.z + bv.z;
    o[3] = (v3 - mean) * rstd * gv.w + bv.w;
    *(float4*)&out[base + t * 4] = make_float4(o[0], o[1], o[2], o[3]);
    if (oh) {
        uint2 ho;
        ho.x = pack_h2(o[0], o[1]);
        ho.y = pack_h2(o[2], o[3]);
        *(uint2*)&oh[base + t * 4] = ho;
    }
}

// ---------------- launch ---------------------------------------------------------
extern "C" void kernel_launch(void* const* d_in, const int* in_sizes, int n_in,
                              void* d_out, int out_size)
{
    (void)in_sizes; (void)n_in; (void)out_size;
    const float* x    = (const float*)d_in[0];
    const float* ipw  = (const float*)d_in[1];
    const float* ipb  = (const float*)d_in[2];
    const float* opw  = (const float*)d_in[3];
    const float* opb  = (const float*)d_in[4];
    const float* ln1g = (const float*)d_in[5];
    const float* ln1b = (const float*)d_in[6];
    const float* w1   = (const float*)d_in[7];
    const float* b1   = (const float*)d_in[8];
    const float* w2   = (const float*)d_in[9];
    const float* b2   = (const float*)d_in[10];
    const float* ln2g = (const float*)d_in[11];
    const float* ln2b = (const float*)d_in[12];
    float* out = (float*)d_out;

    float *tmp, *x1;
    cudaGetSymbolAddress((void**)&tmp, g_tmp);
    cudaGetSymbolAddress((void**)&x1,  g_x1);

    __half *a1h, *a2h, *x1h, *hh, *qkh, *vh, *wih, *woh, *w1h, *w2h;
    cudaGetSymbolAddress((void**)&a1h, g_a1h);
    cudaGetSymbolAddress((void**)&a2h, g_a2h);
    cudaGetSymbolAddress((void**)&x1h, g_x1h);
    cudaGetSymbolAddress((void**)&hh,  g_hh);
    cudaGetSymbolAddress((void**)&qkh, g_qkh);
    cudaGetSymbolAddress((void**)&vh,  g_vh);
    cudaGetSymbolAddress((void**)&wih, g_wih); cudaGetSymbolAddress((void**)&woh, g_woh);
    cudaGetSymbolAddress((void**)&w1h, g_w1h); cudaGetSymbolAddress((void**)&w2h, g_w2h);

    cudaFuncSetAttribute(gemm_mma_kernel<0,0,1>,
                         cudaFuncAttributeMaxDynamicSharedMemorySize, GEMM_SMEM);
    cudaFuncSetAttribute(gemm_mma_kernel<0,1,0>,
                         cudaFuncAttributeMaxDynamicSharedMemorySize, GEMM_SMEM);
    cudaFuncSetAttribute(gemm_mma_kernel<1,1,0>,
                         cudaFuncAttributeMaxDynamicSharedMemorySize, GEMM_SMEM);
    cudaFuncSetAttribute(attn_mma_kernel,
                         cudaFuncAttributeMaxDynamicSharedMemorySize, ATTN_SMEM);

    cudaStream_t s0 = 0, s2 = g_sp.s2;

    cudaEventRecord(g_sp.eStart, s0);
    cudaStreamWaitEvent(s2, g_sp.eStart, 0);

    // 0: RoPE(x) -> a1h, fp16 x -> a2h   (s0)
    rope_conv_kernel<<<BS, 256, 0, s0>>>(x, a1h, a2h);
    cudaEventRecord(g_sp.eR, s0);

    // 1: in_proj weight conv (s2)
    conv_kernel<<<(3 * E_ * E_) / 1024, 256, 0, s2>>>(ipw, wih);
    cudaEventRecord(g_sp.eWih, s2);

    // 2: fused Q|K GEMM (s0)
    cudaStreamWaitEvent(s0, g_sp.eWih, 0);
    gemm_mma_kernel<0,1,0><<<dim3(16, 64), 256, GEMM_SMEM, s0>>>(
        a1h, wih, ipb, nullptr, nullptr, qkh, BS, 2 * E_, E_);

    // 3: V GEMM (s2)
    cudaStreamWaitEvent(s2, g_sp.eR, 0);
    gemm_mma_kernel<0,1,0><<<dim3(8, 64), 256, GEMM_SMEM, s2>>>(
        a2h, wih + (size_t)2*E_*E_, ipb + 2 * E_, nullptr, nullptr, vh, BS, E_, E_);
    cudaEventRecord(g_sp.eV, s2);

    // 4: out_proj weight conv (s2)
    conv_kernel<<<(E_ * E_) / 1024, 256, 0, s2>>>(opw, woh);

    // 5: attention (s0) -> ctx into a2h
    cudaStreamWaitEvent(s0, g_sp.eV, 0);
    attn_mma_kernel<<<dim3(SS / 128, NH, BB), 256, ATTN_SMEM, s0>>>(qkh, vh, a2h);

    // 6,7: FFN weight convs (s2)
    conv_kernel<<<(FF * E_) / 1024, 256, 0, s2>>>(w1, w1h);
    conv_kernel<<<(FF * E_) / 1024, 256, 0, s2>>>(w2, w2h);
    cudaEventRecord(g_sp.eW2, s2);

    cudaStreamWaitEvent(s0, g_sp.eW2, 0);

    // 8: out-proj GEMM (+residual x fused); 9: LN1
    gemm_mma_kernel<0,0,1><<<dim3(8, 64), 256, GEMM_SMEM, s0>>>(
        a2h, woh, opb, x, tmp, nullptr, BS, E_, E_);
    ln_kernel<<<BS, 256, 0, s0>>>(tmp, ln1g, ln1b, x1, x1h);

    // 10-12: FFN (+residual x1 fused in ffn2) + LN2
    gemm_mma_kernel<1,1,0><<<dim3(32, 64), 256, GEMM_SMEM, s0>>>(
        x1h, w1h, b1, nullptr, nullptr, hh, BS, FF, E_);
    gemm_mma_kernel<0,0,1><<<dim3(8, 64), 256, GEMM_SMEM, s0>>>(
        hh, w2h, b2, x1, tmp, nullptr, BS, E_, FF);
    ln_kernel<<<BS, 256, 0, s0>>>(tmp, ln2g, ln2b, out, nullptr);
}